// round 1
// baseline (speedup 1.0000x reference)
#include <cuda_runtime.h>

#define SEQ 4096
#define EMB 768
#define NH 12
#define HD 64

// scratch (allocation-free rule: __device__ globals)
__device__ float g_q[NH * SEQ * HD];
__device__ float g_k[NH * SEQ * HD];
__device__ float g_v[NH * SEQ * HD];
__device__ float g_ctx[SEQ * EMB];

// ---------------------------------------------------------------------------
// Fused QKV projection GEMM: out[s][f] = sum_e x[s][e] * W[e][f]
// BM=64, BN=64, BK=16, 256 threads, 4x4 microtile.
// Writes into [h][s][d] layout (BN==HD so each block covers exactly one head).
// ---------------------------------------------------------------------------
__global__ __launch_bounds__(256) void qkv_gemm_kernel(
    const float* __restrict__ x,
    const float* __restrict__ Wq,
    const float* __restrict__ Wk,
    const float* __restrict__ Wv)
{
    __shared__ float As[16 * 64];   // As[k][m]
    __shared__ float Bs[16 * 64];   // Bs[k][n]

    const float* W   = (blockIdx.z == 0) ? Wq : (blockIdx.z == 1) ? Wk : Wv;
    float*       out = (blockIdx.z == 0) ? g_q : (blockIdx.z == 1) ? g_k : g_v;

    const int m0 = blockIdx.y * 64;
    const int n0 = blockIdx.x * 64;   // == head * 64
    const int h  = n0 >> 6;

    const int tid   = threadIdx.x;
    const int a_row = tid >> 2;       // 0..63
    const int a_c4  = tid & 3;        // 0..3  (k-group of 4)
    const int b_row = tid >> 4;       // 0..15 (k)
    const int b_c4  = tid & 15;       // 0..15 (n-group of 4)
    const int ty    = tid >> 4;       // 0..15 (m microtile)
    const int tx    = tid & 15;       // 0..15 (n microtile)

    float c[4][4];
    #pragma unroll
    for (int i = 0; i < 4; i++)
        #pragma unroll
        for (int j = 0; j < 4; j++) c[i][j] = 0.f;

    for (int k0 = 0; k0 < EMB; k0 += 16) {
        float4 av = *(const float4*)(x + (m0 + a_row) * EMB + k0 + a_c4 * 4);
        float4 bv = *(const float4*)(W + (k0 + b_row) * EMB + n0 + b_c4 * 4);
        __syncthreads();
        As[(a_c4 * 4 + 0) * 64 + a_row] = av.x;
        As[(a_c4 * 4 + 1) * 64 + a_row] = av.y;
        As[(a_c4 * 4 + 2) * 64 + a_row] = av.z;
        As[(a_c4 * 4 + 3) * 64 + a_row] = av.w;
        *(float4*)(Bs + b_row * 64 + b_c4 * 4) = bv;
        __syncthreads();

        #pragma unroll
        for (int kk = 0; kk < 16; kk++) {
            float4 a = *(const float4*)(As + kk * 64 + ty * 4);
            float4 b = *(const float4*)(Bs + kk * 64 + tx * 4);
            float ar[4] = {a.x, a.y, a.z, a.w};
            float br[4] = {b.x, b.y, b.z, b.w};
            #pragma unroll
            for (int i = 0; i < 4; i++)
                #pragma unroll
                for (int j = 0; j < 4; j++)
                    c[i][j] += ar[i] * br[j];
        }
    }

    #pragma unroll
    for (int i = 0; i < 4; i++) {
        const int row = m0 + ty * 4 + i;
        #pragma unroll
        for (int j = 0; j < 4; j++) {
            const int d = tx * 4 + j;   // n0 is head-aligned
            out[(h * SEQ + row) * HD + d] = c[i][j];
        }
    }
}

// ---------------------------------------------------------------------------
// Flash attention, causal. One block = (head, 64-query tile), 64 threads,
// one thread per query row. q-row and o-accumulator in registers.
// Two-pass per key-tile with scores staged in xor-swizzled smem.
// ---------------------------------------------------------------------------
__global__ __launch_bounds__(64) void attn_kernel()
{
    extern __shared__ float sm[];
    float* Ks = sm;              // 64x64
    float* Vs = sm + 4096;       // 64x64
    float* Sc = sm + 8192;       // 64x64, xor swizzle

    const int h  = blockIdx.y;
    const int qt = (gridDim.x - 1) - blockIdx.x;   // big tiles first
    const int t  = threadIdx.x;
    const int i  = qt * 64 + t;                    // global query row
    const int sw = t & 31;

    float q[64];
    {
        const float4* qp = (const float4*)(g_q + (h * SEQ + i) * HD);
        #pragma unroll
        for (int d4 = 0; d4 < 16; d4++) {
            float4 v = qp[d4];
            q[d4 * 4 + 0] = v.x; q[d4 * 4 + 1] = v.y;
            q[d4 * 4 + 2] = v.z; q[d4 * 4 + 3] = v.w;
        }
    }

    float o[64];
    #pragma unroll
    for (int d = 0; d < 64; d++) o[d] = 0.f;
    float m = -1e30f, l = 0.f;
    const float scale = 0.125f;   // 1/sqrt(64)

    for (int kt = 0; kt <= qt; kt++) {
        __syncthreads();   // protect smem vs previous iteration's readers
        {
            const float4* kg = (const float4*)(g_k + (h * SEQ + kt * 64) * HD);
            const float4* vg = (const float4*)(g_v + (h * SEQ + kt * 64) * HD);
            float4* Ks4 = (float4*)Ks;
            float4* Vs4 = (float4*)Vs;
            #pragma unroll
            for (int r = 0; r < 16; r++) {
                Ks4[r * 64 + t] = kg[r * 64 + t];
                Vs4[r * 64 + t] = vg[r * 64 + t];
            }
        }
        __syncthreads();

        // pass 1: scores + tile max
        const int jmax = (kt == qt) ? (t + 1) : 64;   // causal
        float tm = -1e30f;
        for (int j = 0; j < 64; j++) {
            const float4* kr = (const float4*)(Ks + j * 64);
            float a0 = 0.f, a1 = 0.f, a2 = 0.f, a3 = 0.f;
            #pragma unroll
            for (int d4 = 0; d4 < 16; d4++) {
                float4 kk = kr[d4];
                a0 += q[d4 * 4 + 0] * kk.x;
                a1 += q[d4 * 4 + 1] * kk.y;
                a2 += q[d4 * 4 + 2] * kk.z;
                a3 += q[d4 * 4 + 3] * kk.w;
            }
            float s = ((a0 + a1) + (a2 + a3)) * scale;
            if (j >= jmax) s = -1e30f;
            tm = fmaxf(tm, s);
            Sc[t * 64 + (j ^ sw)] = s;
        }

        // pass 2: online-softmax accumulate
        const float mnew = fmaxf(m, tm);
        const float corr = __expf(m - mnew);
        l *= corr;
        #pragma unroll
        for (int d = 0; d < 64; d++) o[d] *= corr;
        m = mnew;

        for (int j = 0; j < 64; j++) {
            const float p = __expf(Sc[t * 64 + (j ^ sw)] - m);
            l += p;
            const float4* vr = (const float4*)(Vs + j * 64);
            #pragma unroll
            for (int d4 = 0; d4 < 16; d4++) {
                float4 vv = vr[d4];
                o[d4 * 4 + 0] += p * vv.x;
                o[d4 * 4 + 1] += p * vv.y;
                o[d4 * 4 + 2] += p * vv.z;
                o[d4 * 4 + 3] += p * vv.w;
            }
        }
    }

    const float inv = 1.f / l;
    float4* cp = (float4*)(g_ctx + i * EMB + h * HD);
    #pragma unroll
    for (int d4 = 0; d4 < 16; d4++) {
        float4 v;
        v.x = o[d4 * 4 + 0] * inv;
        v.y = o[d4 * 4 + 1] * inv;
        v.z = o[d4 * 4 + 2] * inv;
        v.w = o[d4 * 4 + 3] * inv;
        cp[d4] = v;
    }
}

// ---------------------------------------------------------------------------
// Output projection + bias: out[s][f] = sum_e ctx[s][e]*Wo[e][f] + bo[f]
// ---------------------------------------------------------------------------
__global__ __launch_bounds__(256) void out_gemm_kernel(
    const float* __restrict__ Wo,
    const float* __restrict__ bo,
    float* __restrict__ out)
{
    __shared__ float As[16 * 64];
    __shared__ float Bs[16 * 64];

    const int m0 = blockIdx.y * 64;
    const int n0 = blockIdx.x * 64;

    const int tid   = threadIdx.x;
    const int a_row = tid >> 2;
    const int a_c4  = tid & 3;
    const int b_row = tid >> 4;
    const int b_c4  = tid & 15;
    const int ty    = tid >> 4;
    const int tx    = tid & 15;

    float c[4][4];
    #pragma unroll
    for (int i = 0; i < 4; i++)
        #pragma unroll
        for (int j = 0; j < 4; j++) c[i][j] = 0.f;

    for (int k0 = 0; k0 < EMB; k0 += 16) {
        float4 av = *(const float4*)(g_ctx + (m0 + a_row) * EMB + k0 + a_c4 * 4);
        float4 bv = *(const float4*)(Wo + (k0 + b_row) * EMB + n0 + b_c4 * 4);
        __syncthreads();
        As[(a_c4 * 4 + 0) * 64 + a_row] = av.x;
        As[(a_c4 * 4 + 1) * 64 + a_row] = av.y;
        As[(a_c4 * 4 + 2) * 64 + a_row] = av.z;
        As[(a_c4 * 4 + 3) * 64 + a_row] = av.w;
        *(float4*)(Bs + b_row * 64 + b_c4 * 4) = bv;
        __syncthreads();

        #pragma unroll
        for (int kk = 0; kk < 16; kk++) {
            float4 a = *(const float4*)(As + kk * 64 + ty * 4);
            float4 b = *(const float4*)(Bs + kk * 64 + tx * 4);
            float ar[4] = {a.x, a.y, a.z, a.w};
            float br[4] = {b.x, b.y, b.z, b.w};
            #pragma unroll
            for (int i = 0; i < 4; i++)
                #pragma unroll
                for (int j = 0; j < 4; j++)
                    c[i][j] += ar[i] * br[j];
        }
    }

    #pragma unroll
    for (int i = 0; i < 4; i++) {
        const int row = m0 + ty * 4 + i;
        #pragma unroll
        for (int j = 0; j < 4; j++) {
            const int col = n0 + tx * 4 + j;
            out[row * EMB + col] = c[i][j] + bo[col];
        }
    }
}

// ---------------------------------------------------------------------------
extern "C" void kernel_launch(void* const* d_in, const int* in_sizes, int n_in,
                              void* d_out, int out_size)
{
    (void)in_sizes; (void)n_in; (void)out_size;
    const float* x  = (const float*)d_in[0];
    const float* Wq = (const float*)d_in[1];
    const float* Wk = (const float*)d_in[2];
    const float* Wv = (const float*)d_in[3];
    const float* Wo = (const float*)d_in[4];
    const float* bo = (const float*)d_in[5];
    // d_in[6] = causal mask, structurally known -> unused

    qkv_gemm_kernel<<<dim3(EMB / 64, SEQ / 64, 3), 256>>>(x, Wq, Wk, Wv);
    attn_kernel<<<dim3(SEQ / 64, NH), 64, 3 * 64 * 64 * sizeof(float)>>>();
    out_gemm_kernel<<<dim3(EMB / 64, SEQ / 64), 256>>>(Wo, bo, (float*)d_out);
}

// round 3
// speedup vs baseline: 3.7027x; 3.7027x over previous
#include <cuda_runtime.h>

#define SEQ 4096
#define EMB 768
#define NH 12
#define HD 64

// scratch (allocation-free rule: __device__ globals)
__device__ float g_q[NH * SEQ * HD];
__device__ float g_k[NH * SEQ * HD];
__device__ float g_v[NH * SEQ * HD];
__device__ float g_ctx[SEQ * EMB];

// ---------------------------------------------------------------------------
// tf32 helpers
// ---------------------------------------------------------------------------
__device__ __forceinline__ float f2tf(float f) {
    unsigned u;
    asm("cvt.rna.tf32.f32 %0, %1;" : "=r"(u) : "f"(f));
    return __uint_as_float(u);
}

__device__ __forceinline__ void mma_tf32(float c[4], const float a[4], const float b[2]) {
    asm volatile(
        "mma.sync.aligned.m16n8k8.row.col.f32.tf32.tf32.f32 "
        "{%0,%1,%2,%3}, {%4,%5,%6,%7}, {%8,%9}, {%0,%1,%2,%3};"
        : "+f"(c[0]), "+f"(c[1]), "+f"(c[2]), "+f"(c[3])
        : "r"(__float_as_uint(a[0])), "r"(__float_as_uint(a[1])),
          "r"(__float_as_uint(a[2])), "r"(__float_as_uint(a[3])),
          "r"(__float_as_uint(b[0])), "r"(__float_as_uint(b[1])));
}

// ---------------------------------------------------------------------------
// GEMM: out[m][n] = sum_k A[m][k] * W[k][n]  (M=4096, N=64 per block, K=768)
// BM=128 BN=64 BK=32, 256 threads = 8 warps (4x2), warp tile 32x32.
// QKV=true:  A = x (host pointer), blockIdx.z selects Wq/Wk/Wv, writes scratch.
// QKV=false: A = g_ctx (device symbol, resolved IN DEVICE CODE), writes out+bias.
// ---------------------------------------------------------------------------
template <bool QKV>
__global__ __launch_bounds__(256) void gemm_kernel(
    const float* __restrict__ Ain,
    const float* __restrict__ W0,
    const float* __restrict__ W1,
    const float* __restrict__ W2,
    const float* __restrict__ bias,
    float* __restrict__ outp)
{
    __shared__ float As[128][36];   // [m][k], pad 36 -> conflict-free frag reads
    __shared__ float Bs[32][72];    // [k][n], pad 72

    const float* A = QKV ? Ain : (const float*)g_ctx;   // device-side symbol use
    const float* W;
    float* out;
    if (QKV) {
        W   = (blockIdx.z == 0) ? W0 : (blockIdx.z == 1) ? W1 : W2;
        out = (blockIdx.z == 0) ? g_q : (blockIdx.z == 1) ? g_k : g_v;
    } else {
        W   = W0;
        out = outp;
    }

    const int m0   = blockIdx.y * 128;
    const int n0   = blockIdx.x * 64;
    const int t    = threadIdx.x;
    const int lane = t & 31;
    const int warp = t >> 5;
    const int wm   = warp >> 1;     // 0..3
    const int wn   = warp & 1;      // 0..1
    const int g    = lane >> 2;     // 0..7
    const int cq   = lane & 3;      // 0..3

    float c[2][4][4];
    #pragma unroll
    for (int mt = 0; mt < 2; mt++)
        #pragma unroll
        for (int nt = 0; nt < 4; nt++)
            #pragma unroll
            for (int i = 0; i < 4; i++) c[mt][nt][i] = 0.f;

    for (int k0 = 0; k0 < EMB; k0 += 32) {
        float4 av[4];
        #pragma unroll
        for (int j = 0; j < 4; j++) {
            const int f = j * 256 + t;
            const int row = f >> 3, kc = f & 7;
            av[j] = *(const float4*)(A + (size_t)(m0 + row) * EMB + k0 + kc * 4);
        }
        float4 bv[2];
        #pragma unroll
        for (int j = 0; j < 2; j++) {
            const int f = j * 256 + t;
            const int kk = f >> 4, nc = f & 15;
            bv[j] = *(const float4*)(W + (size_t)(k0 + kk) * EMB + n0 + nc * 4);
        }
        __syncthreads();
        #pragma unroll
        for (int j = 0; j < 4; j++) {
            const int f = j * 256 + t;
            const int row = f >> 3, kc = f & 7;
            float4 v;
            v.x = f2tf(av[j].x); v.y = f2tf(av[j].y);
            v.z = f2tf(av[j].z); v.w = f2tf(av[j].w);
            *(float4*)&As[row][kc * 4] = v;
        }
        #pragma unroll
        for (int j = 0; j < 2; j++) {
            const int f = j * 256 + t;
            const int kk = f >> 4, nc = f & 15;
            float4 v;
            v.x = f2tf(bv[j].x); v.y = f2tf(bv[j].y);
            v.z = f2tf(bv[j].z); v.w = f2tf(bv[j].w);
            *(float4*)&Bs[kk][nc * 4] = v;
        }
        __syncthreads();

        float aa[2][4][4];
        #pragma unroll
        for (int mt = 0; mt < 2; mt++) {
            const int mr = wm * 32 + mt * 16 + g;
            #pragma unroll
            for (int ks = 0; ks < 4; ks++) {
                aa[mt][ks][0] = As[mr][ks * 8 + cq];
                aa[mt][ks][1] = As[mr + 8][ks * 8 + cq];
                aa[mt][ks][2] = As[mr][ks * 8 + cq + 4];
                aa[mt][ks][3] = As[mr + 8][ks * 8 + cq + 4];
            }
        }
        float bb[4][4][2];
        #pragma unroll
        for (int nt = 0; nt < 4; nt++) {
            const int nc = wn * 32 + nt * 8 + g;
            #pragma unroll
            for (int ks = 0; ks < 4; ks++) {
                bb[nt][ks][0] = Bs[ks * 8 + cq][nc];
                bb[nt][ks][1] = Bs[ks * 8 + cq + 4][nc];
            }
        }
        #pragma unroll
        for (int mt = 0; mt < 2; mt++)
            #pragma unroll
            for (int nt = 0; nt < 4; nt++)
                #pragma unroll
                for (int ks = 0; ks < 4; ks++)
                    mma_tf32(c[mt][nt], aa[mt][ks], bb[nt][ks]);
    }

    #pragma unroll
    for (int mt = 0; mt < 2; mt++) {
        const int row = m0 + wm * 32 + mt * 16 + g;
        #pragma unroll
        for (int nt = 0; nt < 4; nt++) {
            const int col = wn * 32 + nt * 8 + 2 * cq;
            if (QKV) {
                const int h = blockIdx.x;   // BN==HD: one head per n-block
                float2 v0 = make_float2(c[mt][nt][0], c[mt][nt][1]);
                float2 v1 = make_float2(c[mt][nt][2], c[mt][nt][3]);
                *(float2*)(out + ((size_t)h * SEQ + row) * HD + col)     = v0;
                *(float2*)(out + ((size_t)h * SEQ + row + 8) * HD + col) = v1;
            } else {
                const float b0 = bias[n0 + col], b1 = bias[n0 + col + 1];
                float2 v0 = make_float2(c[mt][nt][0] + b0, c[mt][nt][1] + b1);
                float2 v1 = make_float2(c[mt][nt][2] + b0, c[mt][nt][3] + b1);
                *(float2*)(out + (size_t)row * EMB + n0 + col)           = v0;
                *(float2*)(out + ((size_t)row + 8) * EMB + n0 + col)     = v1;
            }
        }
    }
}

// ---------------------------------------------------------------------------
// Flash attention (causal) with tf32 mma. Block = (head, 64-query tile),
// 4 warps x 16 query rows. Q fragments register-resident. K/V tiles in smem
// (tf32-converted, pad 72). P round-trips through smem (pad 68).
// ---------------------------------------------------------------------------
__global__ __launch_bounds__(128) void attn_kernel()
{
    extern __shared__ float sm[];
    float* Ks = sm;                 // [64][72]
    float* Vs = sm + 64 * 72;       // [64][72]
    float* Ps = sm + 2 * 64 * 72;   // [64][68]

    const int h    = blockIdx.y;
    const int qt   = (gridDim.x - 1) - blockIdx.x;   // big tiles first
    const int t    = threadIdx.x;
    const int lane = t & 31;
    const int w    = t >> 5;
    const int g    = lane >> 2;
    const int cq   = lane & 3;

    // Q fragments, pre-scaled by 1/sqrt(D)
    float qa[8][4];
    {
        const int qrow = qt * 64 + w * 16 + g;
        const float* q0 = g_q + ((size_t)h * SEQ + qrow) * HD;
        const float* q1 = g_q + ((size_t)h * SEQ + qrow + 8) * HD;
        #pragma unroll
        for (int ks = 0; ks < 8; ks++) {
            qa[ks][0] = f2tf(0.125f * q0[ks * 8 + cq]);
            qa[ks][1] = f2tf(0.125f * q1[ks * 8 + cq]);
            qa[ks][2] = f2tf(0.125f * q0[ks * 8 + cq + 4]);
            qa[ks][3] = f2tf(0.125f * q1[ks * 8 + cq + 4]);
        }
    }

    float of[8][4];
    #pragma unroll
    for (int nt = 0; nt < 8; nt++)
        #pragma unroll
        for (int i = 0; i < 4; i++) of[nt][i] = 0.f;
    float m0r = -1e30f, m1r = -1e30f, l0 = 0.f, l1 = 0.f;

    for (int kt = 0; kt <= qt; kt++) {
        __syncthreads();   // protect K/V smem vs previous iteration readers
        #pragma unroll
        for (int r = 0; r < 8; r++) {
            const int i = r * 128 + t;
            const int key = i >> 4, d4 = i & 15;
            const size_t base = ((size_t)h * SEQ + kt * 64 + key) * HD + d4 * 4;
            float4 kv = *(const float4*)(g_k + base);
            float4 vv = *(const float4*)(g_v + base);
            float4 kc, vc;
            kc.x = f2tf(kv.x); kc.y = f2tf(kv.y); kc.z = f2tf(kv.z); kc.w = f2tf(kv.w);
            vc.x = f2tf(vv.x); vc.y = f2tf(vv.y); vc.z = f2tf(vv.z); vc.w = f2tf(vv.w);
            *(float4*)&Ks[key * 72 + d4 * 4] = kc;
            *(float4*)&Vs[key * 72 + d4 * 4] = vc;
        }
        __syncthreads();

        // S = Q K^T  (16x64 per warp)
        float sf[8][4];
        #pragma unroll
        for (int nt = 0; nt < 8; nt++) {
            sf[nt][0] = sf[nt][1] = sf[nt][2] = sf[nt][3] = 0.f;
            #pragma unroll
            for (int ks = 0; ks < 8; ks++) {
                float b[2];
                b[0] = Ks[(nt * 8 + g) * 72 + ks * 8 + cq];
                b[1] = Ks[(nt * 8 + g) * 72 + ks * 8 + cq + 4];
                mma_tf32(sf[nt], qa[ks], b);
            }
        }

        // causal mask on diagonal tile
        if (kt == qt) {
            const int q0l = w * 16 + g, q1l = q0l + 8;
            #pragma unroll
            for (int nt = 0; nt < 8; nt++) {
                const int key = nt * 8 + 2 * cq;
                if (key     > q0l) sf[nt][0] = -1e30f;
                if (key + 1 > q0l) sf[nt][1] = -1e30f;
                if (key     > q1l) sf[nt][2] = -1e30f;
                if (key + 1 > q1l) sf[nt][3] = -1e30f;
            }
        }

        // online softmax
        float tm0 = -1e30f, tm1 = -1e30f;
        #pragma unroll
        for (int nt = 0; nt < 8; nt++) {
            tm0 = fmaxf(tm0, fmaxf(sf[nt][0], sf[nt][1]));
            tm1 = fmaxf(tm1, fmaxf(sf[nt][2], sf[nt][3]));
        }
        tm0 = fmaxf(tm0, __shfl_xor_sync(0xffffffffu, tm0, 1));
        tm0 = fmaxf(tm0, __shfl_xor_sync(0xffffffffu, tm0, 2));
        tm1 = fmaxf(tm1, __shfl_xor_sync(0xffffffffu, tm1, 1));
        tm1 = fmaxf(tm1, __shfl_xor_sync(0xffffffffu, tm1, 2));

        const float mn0 = fmaxf(m0r, tm0), mn1 = fmaxf(m1r, tm1);
        const float co0 = __expf(m0r - mn0), co1 = __expf(m1r - mn1);
        m0r = mn0; m1r = mn1;
        l0 *= co0; l1 *= co1;
        #pragma unroll
        for (int nt = 0; nt < 8; nt++) {
            of[nt][0] *= co0; of[nt][1] *= co0;
            of[nt][2] *= co1; of[nt][3] *= co1;
        }

        const int q0l = w * 16 + g;
        #pragma unroll
        for (int nt = 0; nt < 8; nt++) {
            const float p0 = __expf(sf[nt][0] - m0r);
            const float p1 = __expf(sf[nt][1] - m0r);
            const float p2 = __expf(sf[nt][2] - m1r);
            const float p3 = __expf(sf[nt][3] - m1r);
            l0 += p0 + p1;
            l1 += p2 + p3;
            const int key = nt * 8 + 2 * cq;
            *(float2*)&Ps[q0l * 68 + key]       = make_float2(f2tf(p0), f2tf(p1));
            *(float2*)&Ps[(q0l + 8) * 68 + key] = make_float2(f2tf(p2), f2tf(p3));
        }
        __syncwarp();

        // reload P as A fragments
        float pa[8][4];
        #pragma unroll
        for (int ks = 0; ks < 8; ks++) {
            const int qr = w * 16 + g;
            pa[ks][0] = Ps[qr * 68 + ks * 8 + cq];
            pa[ks][1] = Ps[(qr + 8) * 68 + ks * 8 + cq];
            pa[ks][2] = Ps[qr * 68 + ks * 8 + cq + 4];
            pa[ks][3] = Ps[(qr + 8) * 68 + ks * 8 + cq + 4];
        }

        // O += P V
        #pragma unroll
        for (int nt = 0; nt < 8; nt++) {
            #pragma unroll
            for (int ks = 0; ks < 8; ks++) {
                float b[2];
                b[0] = Vs[(ks * 8 + cq) * 72 + nt * 8 + g];
                b[1] = Vs[(ks * 8 + cq + 4) * 72 + nt * 8 + g];
                mma_tf32(of[nt], pa[ks], b);
            }
        }
    }

    // finalize
    l0 += __shfl_xor_sync(0xffffffffu, l0, 1);
    l0 += __shfl_xor_sync(0xffffffffu, l0, 2);
    l1 += __shfl_xor_sync(0xffffffffu, l1, 1);
    l1 += __shfl_xor_sync(0xffffffffu, l1, 2);
    const float inv0 = 1.f / l0, inv1 = 1.f / l1;

    const int row0 = qt * 64 + w * 16 + g;
    #pragma unroll
    for (int nt = 0; nt < 8; nt++) {
        const int d = nt * 8 + 2 * cq;
        *(float2*)(g_ctx + (size_t)row0 * EMB + h * HD + d) =
            make_float2(of[nt][0] * inv0, of[nt][1] * inv0);
        *(float2*)(g_ctx + ((size_t)row0 + 8) * EMB + h * HD + d) =
            make_float2(of[nt][2] * inv1, of[nt][3] * inv1);
    }
}

// ---------------------------------------------------------------------------
extern "C" void kernel_launch(void* const* d_in, const int* in_sizes, int n_in,
                              void* d_out, int out_size)
{
    (void)in_sizes; (void)n_in; (void)out_size;
    const float* x  = (const float*)d_in[0];
    const float* Wq = (const float*)d_in[1];
    const float* Wk = (const float*)d_in[2];
    const float* Wv = (const float*)d_in[3];
    const float* Wo = (const float*)d_in[4];
    const float* bo = (const float*)d_in[5];
    // d_in[6] = causal mask, structurally known -> unused

    const int attn_smem = (2 * 64 * 72 + 64 * 68) * sizeof(float);   // 54272 B
    static int smem_set = 0;
    if (!smem_set) {
        cudaFuncSetAttribute(attn_kernel, cudaFuncAttributeMaxDynamicSharedMemorySize,
                             attn_smem);
        smem_set = 1;
    }

    gemm_kernel<true><<<dim3(EMB / 64, SEQ / 128, 3), 256>>>(x, Wq, Wk, Wv, nullptr, nullptr);
    attn_kernel<<<dim3(SEQ / 64, NH), 128, attn_smem>>>();
    gemm_kernel<false><<<dim3(EMB / 64, SEQ / 128, 1), 256>>>(nullptr, Wo, nullptr, nullptr, bo, (float*)d_out);
}

// round 4
// speedup vs baseline: 3.7120x; 1.0025x over previous
#include <cuda_runtime.h>

#define SEQ 4096
#define EMB 768
#define NH 12
#define HD 64

// scratch (allocation-free rule: __device__ globals)
__device__ float g_q[NH * SEQ * HD];
__device__ float g_k[NH * SEQ * HD];
__device__ float g_v[NH * SEQ * HD];
__device__ float g_ctx[SEQ * EMB];

// ---------------------------------------------------------------------------
// tf32 helpers
// ---------------------------------------------------------------------------
__device__ __forceinline__ float f2tf(float f) {
    unsigned u;
    asm("cvt.rna.tf32.f32 %0, %1;" : "=r"(u) : "f"(f));
    return __uint_as_float(u);
}

__device__ __forceinline__ void mma_tf32(float c[4], const float a[4], const float b[2]) {
    asm volatile(
        "mma.sync.aligned.m16n8k8.row.col.f32.tf32.tf32.f32 "
        "{%0,%1,%2,%3}, {%4,%5,%6,%7}, {%8,%9}, {%0,%1,%2,%3};"
        : "+f"(c[0]), "+f"(c[1]), "+f"(c[2]), "+f"(c[3])
        : "r"(__float_as_uint(a[0])), "r"(__float_as_uint(a[1])),
          "r"(__float_as_uint(a[2])), "r"(__float_as_uint(a[3])),
          "r"(__float_as_uint(b[0])), "r"(__float_as_uint(b[1])));
}

// ---------------------------------------------------------------------------
// GEMM: out[m][n] = sum_k A[m][k] * W[k][n]  (M=4096, N=64 per block, K=768)
// BM=128 BN=64 BK=32, 256 threads = 8 warps (4x2), warp tile 32x32.
// QKV=true:  A = x (host pointer), blockIdx.z selects Wq/Wk/Wv, writes scratch.
// QKV=false: A = g_ctx (device symbol, resolved IN DEVICE CODE), writes out+bias.
// ---------------------------------------------------------------------------
template <bool QKV>
__global__ __launch_bounds__(256) void gemm_kernel(
    const float* __restrict__ Ain,
    const float* __restrict__ W0,
    const float* __restrict__ W1,
    const float* __restrict__ W2,
    const float* __restrict__ bias,
    float* __restrict__ outp)
{
    __shared__ float As[128][36];   // [m][k], pad 36 -> conflict-free frag reads
    __shared__ float Bs[32][72];    // [k][n], pad 72

    const float* A = QKV ? Ain : (const float*)g_ctx;   // device-side symbol use
    const float* W;
    float* out;
    if (QKV) {
        W   = (blockIdx.z == 0) ? W0 : (blockIdx.z == 1) ? W1 : W2;
        out = (blockIdx.z == 0) ? g_q : (blockIdx.z == 1) ? g_k : g_v;
    } else {
        W   = W0;
        out = outp;
    }

    const int m0   = blockIdx.y * 128;
    const int n0   = blockIdx.x * 64;
    const int t    = threadIdx.x;
    const int lane = t & 31;
    const int warp = t >> 5;
    const int wm   = warp >> 1;     // 0..3
    const int wn   = warp & 1;      // 0..1
    const int g    = lane >> 2;     // 0..7
    const int cq   = lane & 3;      // 0..3

    float c[2][4][4];
    #pragma unroll
    for (int mt = 0; mt < 2; mt++)
        #pragma unroll
        for (int nt = 0; nt < 4; nt++)
            #pragma unroll
            for (int i = 0; i < 4; i++) c[mt][nt][i] = 0.f;

    for (int k0 = 0; k0 < EMB; k0 += 32) {
        float4 av[4];
        #pragma unroll
        for (int j = 0; j < 4; j++) {
            const int f = j * 256 + t;
            const int row = f >> 3, kc = f & 7;
            av[j] = *(const float4*)(A + (size_t)(m0 + row) * EMB + k0 + kc * 4);
        }
        float4 bv[2];
        #pragma unroll
        for (int j = 0; j < 2; j++) {
            const int f = j * 256 + t;
            const int kk = f >> 4, nc = f & 15;
            bv[j] = *(const float4*)(W + (size_t)(k0 + kk) * EMB + n0 + nc * 4);
        }
        __syncthreads();
        #pragma unroll
        for (int j = 0; j < 4; j++) {
            const int f = j * 256 + t;
            const int row = f >> 3, kc = f & 7;
            float4 v;
            v.x = f2tf(av[j].x); v.y = f2tf(av[j].y);
            v.z = f2tf(av[j].z); v.w = f2tf(av[j].w);
            *(float4*)&As[row][kc * 4] = v;
        }
        #pragma unroll
        for (int j = 0; j < 2; j++) {
            const int f = j * 256 + t;
            const int kk = f >> 4, nc = f & 15;
            float4 v;
            v.x = f2tf(bv[j].x); v.y = f2tf(bv[j].y);
            v.z = f2tf(bv[j].z); v.w = f2tf(bv[j].w);
            *(float4*)&Bs[kk][nc * 4] = v;
        }
        __syncthreads();

        float aa[2][4][4];
        #pragma unroll
        for (int mt = 0; mt < 2; mt++) {
            const int mr = wm * 32 + mt * 16 + g;
            #pragma unroll
            for (int ks = 0; ks < 4; ks++) {
                aa[mt][ks][0] = As[mr][ks * 8 + cq];
                aa[mt][ks][1] = As[mr + 8][ks * 8 + cq];
                aa[mt][ks][2] = As[mr][ks * 8 + cq + 4];
                aa[mt][ks][3] = As[mr + 8][ks * 8 + cq + 4];
            }
        }
        float bb[4][4][2];
        #pragma unroll
        for (int nt = 0; nt < 4; nt++) {
            const int nc = wn * 32 + nt * 8 + g;
            #pragma unroll
            for (int ks = 0; ks < 4; ks++) {
                bb[nt][ks][0] = Bs[ks * 8 + cq][nc];
                bb[nt][ks][1] = Bs[ks * 8 + cq + 4][nc];
            }
        }
        #pragma unroll
        for (int mt = 0; mt < 2; mt++)
            #pragma unroll
            for (int nt = 0; nt < 4; nt++)
                #pragma unroll
                for (int ks = 0; ks < 4; ks++)
                    mma_tf32(c[mt][nt], aa[mt][ks], bb[nt][ks]);
    }

    #pragma unroll
    for (int mt = 0; mt < 2; mt++) {
        const int row = m0 + wm * 32 + mt * 16 + g;
        #pragma unroll
        for (int nt = 0; nt < 4; nt++) {
            const int col = wn * 32 + nt * 8 + 2 * cq;
            if (QKV) {
                const int h = blockIdx.x;   // BN==HD: one head per n-block
                float2 v0 = make_float2(c[mt][nt][0], c[mt][nt][1]);
                float2 v1 = make_float2(c[mt][nt][2], c[mt][nt][3]);
                *(float2*)(out + ((size_t)h * SEQ + row) * HD + col)     = v0;
                *(float2*)(out + ((size_t)h * SEQ + row + 8) * HD + col) = v1;
            } else {
                const float b0 = bias[n0 + col], b1 = bias[n0 + col + 1];
                float2 v0 = make_float2(c[mt][nt][0] + b0, c[mt][nt][1] + b1);
                float2 v1 = make_float2(c[mt][nt][2] + b0, c[mt][nt][3] + b1);
                *(float2*)(out + (size_t)row * EMB + n0 + col)           = v0;
                *(float2*)(out + ((size_t)row + 8) * EMB + n0 + col)     = v1;
            }
        }
    }
}

// ---------------------------------------------------------------------------
// Flash attention (causal) with tf32 mma. Block = (head, 64-query tile),
// 4 warps x 16 query rows. Q fragments register-resident. K/V tiles in smem
// (tf32-converted, pad 72). P round-trips through smem (pad 68).
// ---------------------------------------------------------------------------
__global__ __launch_bounds__(128) void attn_kernel()
{
    extern __shared__ float sm[];
    float* Ks = sm;                 // [64][72]
    float* Vs = sm + 64 * 72;       // [64][72]
    float* Ps = sm + 2 * 64 * 72;   // [64][68]

    const int h    = blockIdx.y;
    const int qt   = (gridDim.x - 1) - blockIdx.x;   // big tiles first
    const int t    = threadIdx.x;
    const int lane = t & 31;
    const int w    = t >> 5;
    const int g    = lane >> 2;
    const int cq   = lane & 3;

    // Q fragments, pre-scaled by 1/sqrt(D)
    float qa[8][4];
    {
        const int qrow = qt * 64 + w * 16 + g;
        const float* q0 = g_q + ((size_t)h * SEQ + qrow) * HD;
        const float* q1 = g_q + ((size_t)h * SEQ + qrow + 8) * HD;
        #pragma unroll
        for (int ks = 0; ks < 8; ks++) {
            qa[ks][0] = f2tf(0.125f * q0[ks * 8 + cq]);
            qa[ks][1] = f2tf(0.125f * q1[ks * 8 + cq]);
            qa[ks][2] = f2tf(0.125f * q0[ks * 8 + cq + 4]);
            qa[ks][3] = f2tf(0.125f * q1[ks * 8 + cq + 4]);
        }
    }

    float of[8][4];
    #pragma unroll
    for (int nt = 0; nt < 8; nt++)
        #pragma unroll
        for (int i = 0; i < 4; i++) of[nt][i] = 0.f;
    float m0r = -1e30f, m1r = -1e30f, l0 = 0.f, l1 = 0.f;

    for (int kt = 0; kt <= qt; kt++) {
        __syncthreads();   // protect K/V smem vs previous iteration readers
        #pragma unroll
        for (int r = 0; r < 8; r++) {
            const int i = r * 128 + t;
            const int key = i >> 4, d4 = i & 15;
            const size_t base = ((size_t)h * SEQ + kt * 64 + key) * HD + d4 * 4;
            float4 kv = *(const float4*)(g_k + base);
            float4 vv = *(const float4*)(g_v + base);
            float4 kc, vc;
            kc.x = f2tf(kv.x); kc.y = f2tf(kv.y); kc.z = f2tf(kv.z); kc.w = f2tf(kv.w);
            vc.x = f2tf(vv.x); vc.y = f2tf(vv.y); vc.z = f2tf(vv.z); vc.w = f2tf(vv.w);
            *(float4*)&Ks[key * 72 + d4 * 4] = kc;
            *(float4*)&Vs[key * 72 + d4 * 4] = vc;
        }
        __syncthreads();

        // S = Q K^T  (16x64 per warp)
        float sf[8][4];
        #pragma unroll
        for (int nt = 0; nt < 8; nt++) {
            sf[nt][0] = sf[nt][1] = sf[nt][2] = sf[nt][3] = 0.f;
            #pragma unroll
            for (int ks = 0; ks < 8; ks++) {
                float b[2];
                b[0] = Ks[(nt * 8 + g) * 72 + ks * 8 + cq];
                b[1] = Ks[(nt * 8 + g) * 72 + ks * 8 + cq + 4];
                mma_tf32(sf[nt], qa[ks], b);
            }
        }

        // causal mask on diagonal tile
        if (kt == qt) {
            const int q0l = w * 16 + g, q1l = q0l + 8;
            #pragma unroll
            for (int nt = 0; nt < 8; nt++) {
                const int key = nt * 8 + 2 * cq;
                if (key     > q0l) sf[nt][0] = -1e30f;
                if (key + 1 > q0l) sf[nt][1] = -1e30f;
                if (key     > q1l) sf[nt][2] = -1e30f;
                if (key + 1 > q1l) sf[nt][3] = -1e30f;
            }
        }

        // online softmax
        float tm0 = -1e30f, tm1 = -1e30f;
        #pragma unroll
        for (int nt = 0; nt < 8; nt++) {
            tm0 = fmaxf(tm0, fmaxf(sf[nt][0], sf[nt][1]));
            tm1 = fmaxf(tm1, fmaxf(sf[nt][2], sf[nt][3]));
        }
        tm0 = fmaxf(tm0, __shfl_xor_sync(0xffffffffu, tm0, 1));
        tm0 = fmaxf(tm0, __shfl_xor_sync(0xffffffffu, tm0, 2));
        tm1 = fmaxf(tm1, __shfl_xor_sync(0xffffffffu, tm1, 1));
        tm1 = fmaxf(tm1, __shfl_xor_sync(0xffffffffu, tm1, 2));

        const float mn0 = fmaxf(m0r, tm0), mn1 = fmaxf(m1r, tm1);
        const float co0 = __expf(m0r - mn0), co1 = __expf(m1r - mn1);
        m0r = mn0; m1r = mn1;
        l0 *= co0; l1 *= co1;
        #pragma unroll
        for (int nt = 0; nt < 8; nt++) {
            of[nt][0] *= co0; of[nt][1] *= co0;
            of[nt][2] *= co1; of[nt][3] *= co1;
        }

        const int q0l = w * 16 + g;
        #pragma unroll
        for (int nt = 0; nt < 8; nt++) {
            const float p0 = __expf(sf[nt][0] - m0r);
            const float p1 = __expf(sf[nt][1] - m0r);
            const float p2 = __expf(sf[nt][2] - m1r);
            const float p3 = __expf(sf[nt][3] - m1r);
            l0 += p0 + p1;
            l1 += p2 + p3;
            const int key = nt * 8 + 2 * cq;
            *(float2*)&Ps[q0l * 68 + key]       = make_float2(f2tf(p0), f2tf(p1));
            *(float2*)&Ps[(q0l + 8) * 68 + key] = make_float2(f2tf(p2), f2tf(p3));
        }
        __syncwarp();

        // reload P as A fragments
        float pa[8][4];
        #pragma unroll
        for (int ks = 0; ks < 8; ks++) {
            const int qr = w * 16 + g;
            pa[ks][0] = Ps[qr * 68 + ks * 8 + cq];
            pa[ks][1] = Ps[(qr + 8) * 68 + ks * 8 + cq];
            pa[ks][2] = Ps[qr * 68 + ks * 8 + cq + 4];
            pa[ks][3] = Ps[(qr + 8) * 68 + ks * 8 + cq + 4];
        }

        // O += P V
        #pragma unroll
        for (int nt = 0; nt < 8; nt++) {
            #pragma unroll
            for (int ks = 0; ks < 8; ks++) {
                float b[2];
                b[0] = Vs[(ks * 8 + cq) * 72 + nt * 8 + g];
                b[1] = Vs[(ks * 8 + cq + 4) * 72 + nt * 8 + g];
                mma_tf32(of[nt], pa[ks], b);
            }
        }
    }

    // finalize
    l0 += __shfl_xor_sync(0xffffffffu, l0, 1);
    l0 += __shfl_xor_sync(0xffffffffu, l0, 2);
    l1 += __shfl_xor_sync(0xffffffffu, l1, 1);
    l1 += __shfl_xor_sync(0xffffffffu, l1, 2);
    const float inv0 = 1.f / l0, inv1 = 1.f / l1;

    const int row0 = qt * 64 + w * 16 + g;
    #pragma unroll
    for (int nt = 0; nt < 8; nt++) {
        const int d = nt * 8 + 2 * cq;
        *(float2*)(g_ctx + (size_t)row0 * EMB + h * HD + d) =
            make_float2(of[nt][0] * inv0, of[nt][1] * inv0);
        *(float2*)(g_ctx + ((size_t)row0 + 8) * EMB + h * HD + d) =
            make_float2(of[nt][2] * inv1, of[nt][3] * inv1);
    }
}

// ---------------------------------------------------------------------------
extern "C" void kernel_launch(void* const* d_in, const int* in_sizes, int n_in,
                              void* d_out, int out_size)
{
    (void)in_sizes; (void)n_in; (void)out_size;
    const float* x  = (const float*)d_in[0];
    const float* Wq = (const float*)d_in[1];
    const float* Wk = (const float*)d_in[2];
    const float* Wv = (const float*)d_in[3];
    const float* Wo = (const float*)d_in[4];
    const float* bo = (const float*)d_in[5];
    // d_in[6] = causal mask, structurally known -> unused

    const int attn_smem = (2 * 64 * 72 + 64 * 68) * sizeof(float);   // 54272 B
    static int smem_set = 0;
    if (!smem_set) {
        cudaFuncSetAttribute(attn_kernel, cudaFuncAttributeMaxDynamicSharedMemorySize,
                             attn_smem);
        smem_set = 1;
    }

    gemm_kernel<true><<<dim3(EMB / 64, SEQ / 128, 3), 256>>>(x, Wq, Wk, Wv, nullptr, nullptr);
    attn_kernel<<<dim3(SEQ / 64, NH), 128, attn_smem>>>();
    gemm_kernel<false><<<dim3(EMB / 64, SEQ / 128, 1), 256>>>(nullptr, Wo, nullptr, nullptr, bo, (float*)d_out);
}

// round 5
// speedup vs baseline: 4.0847x; 1.1004x over previous
#include <cuda_runtime.h>

#define SEQ 4096
#define EMB 768
#define NH 12
#define HD 64

// scratch (allocation-free rule: __device__ globals)
__device__ float g_q[NH * SEQ * HD];    // [h][s][d], tf32, pre-scaled by 0.125
__device__ float g_k[NH * SEQ * HD];    // [h][s][d'], tf32, d' = perm8 within 8-groups
__device__ float g_v[NH * SEQ * HD];    // TRANSPOSED [h][d][s'], tf32, s' = perm8
__device__ float g_ctx[SEQ * EMB];

// ---------------------------------------------------------------------------
// tf32 helpers
// ---------------------------------------------------------------------------
__device__ __forceinline__ float f2tf(float f) {
    unsigned u;
    asm("cvt.rna.tf32.f32 %0, %1;" : "=r"(u) : "f"(f));
    return __uint_as_float(u);
}

__device__ __forceinline__ void mma_tf32(float c[4], const float a[4], const float b[2]) {
    asm volatile(
        "mma.sync.aligned.m16n8k8.row.col.f32.tf32.tf32.f32 "
        "{%0,%1,%2,%3}, {%4,%5,%6,%7}, {%8,%9}, {%0,%1,%2,%3};"
        : "+f"(c[0]), "+f"(c[1]), "+f"(c[2]), "+f"(c[3])
        : "r"(__float_as_uint(a[0])), "r"(__float_as_uint(a[1])),
          "r"(__float_as_uint(a[2])), "r"(__float_as_uint(a[3])),
          "r"(__float_as_uint(b[0])), "r"(__float_as_uint(b[1])));
}

// fragment-pair interleave within an 8-group: j = q + 4h  ->  2q + h
__device__ __forceinline__ int perm8(int j) { return 2 * (j & 3) + (j >> 2); }

// ---------------------------------------------------------------------------
// GEMM: out[m][n] = sum_k A[m][k] * W[k][n]  (M=4096, N=64 per block, K=768)
// BM=128 BN=64 BK=32, 256 threads = 8 warps (4x2), warp tile 32x32.
// QKV=true : blockIdx.z selects Wq/Wk/Wv; epilogue writes tf32 scratch with
//            the layouts documented at the globals above.
// QKV=false: A = g_ctx (device-side symbol), writes out + bias (fp32).
// ---------------------------------------------------------------------------
template <bool QKV>
__global__ __launch_bounds__(256) void gemm_kernel(
    const float* __restrict__ Ain,
    const float* __restrict__ W0,
    const float* __restrict__ W1,
    const float* __restrict__ W2,
    const float* __restrict__ bias,
    float* __restrict__ outp)
{
    __shared__ float As[128][36];
    __shared__ float Bs[32][72];

    const float* A = QKV ? Ain : (const float*)g_ctx;
    const float* W;
    if (QKV) W = (blockIdx.z == 0) ? W0 : (blockIdx.z == 1) ? W1 : W2;
    else     W = W0;

    const int m0   = blockIdx.y * 128;
    const int n0   = blockIdx.x * 64;
    const int t    = threadIdx.x;
    const int lane = t & 31;
    const int warp = t >> 5;
    const int wm   = warp >> 1;
    const int wn   = warp & 1;
    const int g    = lane >> 2;
    const int cq   = lane & 3;

    float c[2][4][4];
    #pragma unroll
    for (int mt = 0; mt < 2; mt++)
        #pragma unroll
        for (int nt = 0; nt < 4; nt++)
            #pragma unroll
            for (int i = 0; i < 4; i++) c[mt][nt][i] = 0.f;

    for (int k0 = 0; k0 < EMB; k0 += 32) {
        float4 av[4];
        #pragma unroll
        for (int j = 0; j < 4; j++) {
            const int f = j * 256 + t;
            const int row = f >> 3, kc = f & 7;
            av[j] = *(const float4*)(A + (size_t)(m0 + row) * EMB + k0 + kc * 4);
        }
        float4 bv[2];
        #pragma unroll
        for (int j = 0; j < 2; j++) {
            const int f = j * 256 + t;
            const int kk = f >> 4, nc = f & 15;
            bv[j] = *(const float4*)(W + (size_t)(k0 + kk) * EMB + n0 + nc * 4);
        }
        __syncthreads();
        #pragma unroll
        for (int j = 0; j < 4; j++) {
            const int f = j * 256 + t;
            const int row = f >> 3, kc = f & 7;
            float4 v;
            v.x = f2tf(av[j].x); v.y = f2tf(av[j].y);
            v.z = f2tf(av[j].z); v.w = f2tf(av[j].w);
            *(float4*)&As[row][kc * 4] = v;
        }
        #pragma unroll
        for (int j = 0; j < 2; j++) {
            const int f = j * 256 + t;
            const int kk = f >> 4, nc = f & 15;
            float4 v;
            v.x = f2tf(bv[j].x); v.y = f2tf(bv[j].y);
            v.z = f2tf(bv[j].z); v.w = f2tf(bv[j].w);
            *(float4*)&Bs[kk][nc * 4] = v;
        }
        __syncthreads();

        float aa[2][4][4];
        #pragma unroll
        for (int mt = 0; mt < 2; mt++) {
            const int mr = wm * 32 + mt * 16 + g;
            #pragma unroll
            for (int ks = 0; ks < 4; ks++) {
                aa[mt][ks][0] = As[mr][ks * 8 + cq];
                aa[mt][ks][1] = As[mr + 8][ks * 8 + cq];
                aa[mt][ks][2] = As[mr][ks * 8 + cq + 4];
                aa[mt][ks][3] = As[mr + 8][ks * 8 + cq + 4];
            }
        }
        float bb[4][4][2];
        #pragma unroll
        for (int nt = 0; nt < 4; nt++) {
            const int nc = wn * 32 + nt * 8 + g;
            #pragma unroll
            for (int ks = 0; ks < 4; ks++) {
                bb[nt][ks][0] = Bs[ks * 8 + cq][nc];
                bb[nt][ks][1] = Bs[ks * 8 + cq + 4][nc];
            }
        }
        #pragma unroll
        for (int mt = 0; mt < 2; mt++)
            #pragma unroll
            for (int nt = 0; nt < 4; nt++)
                #pragma unroll
                for (int ks = 0; ks < 4; ks++)
                    mma_tf32(c[mt][nt], aa[mt][ks], bb[nt][ks]);
    }

    #pragma unroll
    for (int mt = 0; mt < 2; mt++) {
        const int row = m0 + wm * 32 + mt * 16 + g;
        #pragma unroll
        for (int nt = 0; nt < 4; nt++) {
            const int col = wn * 32 + nt * 8 + 2 * cq;
            if (QKV) {
                const int h = blockIdx.x;   // BN==HD: one head per n-block
                if (blockIdx.z == 0) {
                    // Q: tf32, pre-scaled by 1/sqrt(D)=0.125 (exact)
                    float2 v0 = make_float2(f2tf(c[mt][nt][0]) * 0.125f,
                                            f2tf(c[mt][nt][1]) * 0.125f);
                    float2 v1 = make_float2(f2tf(c[mt][nt][2]) * 0.125f,
                                            f2tf(c[mt][nt][3]) * 0.125f);
                    *(float2*)(g_q + ((size_t)h * SEQ + row) * HD + col)     = v0;
                    *(float2*)(g_q + ((size_t)h * SEQ + row + 8) * HD + col) = v1;
                } else if (blockIdx.z == 1) {
                    // K: tf32, column-permuted within 8-groups
                    const int cb = wn * 32 + nt * 8;
                    const int p0 = perm8(2 * cq), p1 = perm8(2 * cq + 1);
                    float* r0 = g_k + ((size_t)h * SEQ + row) * HD + cb;
                    float* r1 = g_k + ((size_t)h * SEQ + row + 8) * HD + cb;
                    r0[p0] = f2tf(c[mt][nt][0]);  r0[p1] = f2tf(c[mt][nt][1]);
                    r1[p0] = f2tf(c[mt][nt][2]);  r1[p1] = f2tf(c[mt][nt][3]);
                } else {
                    // V: tf32, TRANSPOSED [h][d][s'], s row-permuted within 8-groups
                    const int sp0 = (row & ~7) + perm8(row & 7);
                    const int sp1 = ((row + 8) & ~7) + perm8(row & 7);
                    const int d0 = col, d1 = col + 1;
                    g_v[((size_t)h * HD + d0) * SEQ + sp0] = f2tf(c[mt][nt][0]);
                    g_v[((size_t)h * HD + d1) * SEQ + sp0] = f2tf(c[mt][nt][1]);
                    g_v[((size_t)h * HD + d0) * SEQ + sp1] = f2tf(c[mt][nt][2]);
                    g_v[((size_t)h * HD + d1) * SEQ + sp1] = f2tf(c[mt][nt][3]);
                }
            } else {
                const float b0 = bias[n0 + col], b1 = bias[n0 + col + 1];
                float2 v0 = make_float2(c[mt][nt][0] + b0, c[mt][nt][1] + b1);
                float2 v1 = make_float2(c[mt][nt][2] + b0, c[mt][nt][3] + b1);
                *(float2*)(outp + (size_t)row * EMB + n0 + col)           = v0;
                *(float2*)(outp + ((size_t)row + 8) * EMB + n0 + col)     = v1;
            }
        }
    }
}

// ---------------------------------------------------------------------------
// Flash attention (causal), tf32 mma, cp.async double-buffered K/V tiles.
// Block = (head, 64-query tile), 4 warps x 16 q-rows, 128 threads.
// smem (floats): Kbuf[2][64*72] | Vbuf[2][64*72] | Ps[64*68]   (89 KB)
// K smem rows = key, cols = d' (permuted)  -> B-frag = LDS.64
// V smem rows = d,   cols = s' (permuted)  -> B-frag = LDS.64
// ---------------------------------------------------------------------------
#define KV_TILE_F 4608            // 64*72 floats per stage
#define ATTN_SMEM ((4 * KV_TILE_F + 64 * 68) * 4)

__global__ __launch_bounds__(128) void attn_kernel()
{
    extern __shared__ float sm[];
    float* Ps = sm + 4 * KV_TILE_F;

    const int h    = blockIdx.y;
    const int qt   = (gridDim.x - 1) - blockIdx.x;   // big tiles first
    const int t    = threadIdx.x;
    const int lane = t & 31;
    const int w    = t >> 5;
    const int g    = lane >> 2;
    const int cq   = lane & 3;

    // Q fragments (gmem already tf32 + 0.125-scaled)
    float qa[8][4];
    {
        const int qrow = qt * 64 + w * 16 + g;
        const float* q0 = g_q + ((size_t)h * SEQ + qrow) * HD;
        const float* q1 = q0 + 8 * HD;
        #pragma unroll
        for (int ks = 0; ks < 8; ks++) {
            qa[ks][0] = q0[ks * 8 + cq];
            qa[ks][1] = q1[ks * 8 + cq];
            qa[ks][2] = q0[ks * 8 + cq + 4];
            qa[ks][3] = q1[ks * 8 + cq + 4];
        }
    }

    float of[8][4];
    #pragma unroll
    for (int nt = 0; nt < 8; nt++)
        #pragma unroll
        for (int i = 0; i < 4; i++) of[nt][i] = 0.f;
    float m0r = -1e30f, m1r = -1e30f, l0 = 0.f, l1 = 0.f;

    const float* kbase = g_k + (size_t)h * SEQ * HD;
    const float* vbase = g_v + (size_t)h * HD * SEQ;

    // async fill of stage st with key-tile kt_ (16 x 16B per thread)
    #define ISSUE_FILL(kt_, st_) do {                                          \
        const float* ksrc = kbase + (size_t)(kt_) * 64 * HD;                   \
        const float* vsrc = vbase + (kt_) * 64;                                \
        float* kdst = sm + (st_) * KV_TILE_F;                                  \
        float* vdst = sm + 2 * KV_TILE_F + (st_) * KV_TILE_F;                  \
        _Pragma("unroll")                                                      \
        for (int j_ = 0; j_ < 8; j_++) {                                       \
            const int c_ = j_ * 128 + t;                                       \
            const int r_ = c_ >> 4, co_ = c_ & 15;                             \
            unsigned kd = (unsigned)__cvta_generic_to_shared(                  \
                              &kdst[r_ * 72 + co_ * 4]);                       \
            asm volatile("cp.async.cg.shared.global [%0], [%1], 16;"           \
                         :: "r"(kd), "l"(ksrc + c_ * 4));                      \
            unsigned vd = (unsigned)__cvta_generic_to_shared(                  \
                              &vdst[r_ * 72 + co_ * 4]);                       \
            asm volatile("cp.async.cg.shared.global [%0], [%1], 16;"           \
                         :: "r"(vd), "l"(vsrc + (size_t)r_ * SEQ + co_ * 4));  \
        }                                                                      \
    } while (0)

    ISSUE_FILL(0, 0);
    asm volatile("cp.async.commit_group;");

    for (int kt = 0; kt <= qt; kt++) {
        const int st = kt & 1;
        if (kt < qt) {
            ISSUE_FILL(kt + 1, st ^ 1);
            asm volatile("cp.async.commit_group;");
            asm volatile("cp.async.wait_group 1;");
        } else {
            asm volatile("cp.async.wait_group 0;");
        }
        __syncthreads();

        const float* Ks  = sm + st * KV_TILE_F;
        const float* Vts = sm + 2 * KV_TILE_F + st * KV_TILE_F;

        // S = Q K^T (16x64 per warp); B-frags as LDS.64 thanks to permuted cols
        float sf[8][4];
        #pragma unroll
        for (int nt = 0; nt < 8; nt++) {
            sf[nt][0] = sf[nt][1] = sf[nt][2] = sf[nt][3] = 0.f;
            #pragma unroll
            for (int ks = 0; ks < 8; ks++) {
                float2 b = *(const float2*)&Ks[(nt * 8 + g) * 72 + ks * 8 + 2 * cq];
                mma_tf32(sf[nt], qa[ks], (const float*)&b);
            }
        }

        // causal mask on diagonal tile
        if (kt == qt) {
            const int q0l = w * 16 + g, q1l = q0l + 8;
            #pragma unroll
            for (int nt = 0; nt < 8; nt++) {
                const int key = nt * 8 + 2 * cq;
                if (key     > q0l) sf[nt][0] = -1e30f;
                if (key + 1 > q0l) sf[nt][1] = -1e30f;
                if (key     > q1l) sf[nt][2] = -1e30f;
                if (key + 1 > q1l) sf[nt][3] = -1e30f;
            }
        }

        // online softmax
        float tm0 = -1e30f, tm1 = -1e30f;
        #pragma unroll
        for (int nt = 0; nt < 8; nt++) {
            tm0 = fmaxf(tm0, fmaxf(sf[nt][0], sf[nt][1]));
            tm1 = fmaxf(tm1, fmaxf(sf[nt][2], sf[nt][3]));
        }
        tm0 = fmaxf(tm0, __shfl_xor_sync(0xffffffffu, tm0, 1));
        tm0 = fmaxf(tm0, __shfl_xor_sync(0xffffffffu, tm0, 2));
        tm1 = fmaxf(tm1, __shfl_xor_sync(0xffffffffu, tm1, 1));
        tm1 = fmaxf(tm1, __shfl_xor_sync(0xffffffffu, tm1, 2));

        const float mn0 = fmaxf(m0r, tm0), mn1 = fmaxf(m1r, tm1);
        const float co0 = __expf(m0r - mn0), co1 = __expf(m1r - mn1);
        m0r = mn0; m1r = mn1;
        l0 *= co0; l1 *= co1;
        #pragma unroll
        for (int nt = 0; nt < 8; nt++) {
            of[nt][0] *= co0; of[nt][1] *= co0;
            of[nt][2] *= co1; of[nt][3] *= co1;
        }

        const int q0l = w * 16 + g;
        #pragma unroll
        for (int nt = 0; nt < 8; nt++) {
            const float p0 = __expf(sf[nt][0] - m0r);
            const float p1 = __expf(sf[nt][1] - m0r);
            const float p2 = __expf(sf[nt][2] - m1r);
            const float p3 = __expf(sf[nt][3] - m1r);
            l0 += p0 + p1;
            l1 += p2 + p3;
            const int key = nt * 8 + 2 * cq;
            *(float2*)&Ps[q0l * 68 + key]       = make_float2(p0, p1);
            *(float2*)&Ps[(q0l + 8) * 68 + key] = make_float2(p2, p3);
        }
        __syncwarp();

        // reload P as A fragments (HMMA reads the tf32 field -> truncation ok)
        float pa[8][4];
        #pragma unroll
        for (int ks = 0; ks < 8; ks++) {
            pa[ks][0] = Ps[q0l * 68 + ks * 8 + cq];
            pa[ks][1] = Ps[(q0l + 8) * 68 + ks * 8 + cq];
            pa[ks][2] = Ps[q0l * 68 + ks * 8 + cq + 4];
            pa[ks][3] = Ps[(q0l + 8) * 68 + ks * 8 + cq + 4];
        }

        // O += P V  (V transposed+permuted -> B-frags as LDS.64)
        #pragma unroll
        for (int nt = 0; nt < 8; nt++) {
            #pragma unroll
            for (int ks = 0; ks < 8; ks++) {
                float2 b = *(const float2*)&Vts[(nt * 8 + g) * 72 + ks * 8 + 2 * cq];
                mma_tf32(of[nt], pa[ks], (const float*)&b);
            }
        }

        __syncthreads();   // compute(st) done before next iter refills buf st
    }

    // finalize
    l0 += __shfl_xor_sync(0xffffffffu, l0, 1);
    l0 += __shfl_xor_sync(0xffffffffu, l0, 2);
    l1 += __shfl_xor_sync(0xffffffffu, l1, 1);
    l1 += __shfl_xor_sync(0xffffffffu, l1, 2);
    const float inv0 = 1.f / l0, inv1 = 1.f / l1;

    const int row0 = qt * 64 + w * 16 + g;
    #pragma unroll
    for (int nt = 0; nt < 8; nt++) {
        const int d = nt * 8 + 2 * cq;
        *(float2*)(g_ctx + (size_t)row0 * EMB + h * HD + d) =
            make_float2(of[nt][0] * inv0, of[nt][1] * inv0);
        *(float2*)(g_ctx + ((size_t)row0 + 8) * EMB + h * HD + d) =
            make_float2(of[nt][2] * inv1, of[nt][3] * inv1);
    }
}

// ---------------------------------------------------------------------------
extern "C" void kernel_launch(void* const* d_in, const int* in_sizes, int n_in,
                              void* d_out, int out_size)
{
    (void)in_sizes; (void)n_in; (void)out_size;
    const float* x  = (const float*)d_in[0];
    const float* Wq = (const float*)d_in[1];
    const float* Wk = (const float*)d_in[2];
    const float* Wv = (const float*)d_in[3];
    const float* Wo = (const float*)d_in[4];
    const float* bo = (const float*)d_in[5];
    // d_in[6] = causal mask, structurally known -> unused

    cudaFuncSetAttribute(attn_kernel, cudaFuncAttributeMaxDynamicSharedMemorySize,
                         ATTN_SMEM);

    gemm_kernel<true><<<dim3(EMB / 64, SEQ / 128, 3), 256>>>(x, Wq, Wk, Wv, nullptr, nullptr);
    attn_kernel<<<dim3(SEQ / 64, NH), 128, ATTN_SMEM>>>();
    gemm_kernel<false><<<dim3(EMB / 64, SEQ / 128, 1), 256>>>(nullptr, Wo, nullptr, nullptr, bo, (float*)d_out);
}

// round 7
// speedup vs baseline: 4.8135x; 1.1784x over previous
#include <cuda_runtime.h>

#define SEQ 4096
#define EMB 768
#define NH 12
#define HD 64

// scratch (allocation-free rule: __device__ globals)
__device__ __align__(16) float g_x [SEQ * EMB];      // tf32-rounded x
__device__ __align__(16) float g_wq[EMB * EMB];      // tf32-rounded weights
__device__ __align__(16) float g_wk[EMB * EMB];
__device__ __align__(16) float g_wv[EMB * EMB];
__device__ __align__(16) float g_wo[EMB * EMB];
__device__ __align__(16) float g_q [NH * SEQ * HD];  // [h][s][d], *0.125/ln2, tf32
__device__ __align__(16) float g_k [NH * SEQ * HD];  // [h][s][d], tf32
__device__ __align__(16) float g_v [NH * SEQ * HD];  // TRANSPOSED [h][d][s], tf32
__device__ __align__(16) float g_ctx[SEQ * EMB];     // [s][e], tf32

// ---------------------------------------------------------------------------
// helpers
// ---------------------------------------------------------------------------
__device__ __forceinline__ float f2tf(float f) {
    unsigned u;
    asm("cvt.rna.tf32.f32 %0, %1;" : "=r"(u) : "f"(f));
    return __uint_as_float(u);
}

__device__ __forceinline__ float ex2f(float x) {
    float y;
    asm("ex2.approx.f32 %0, %1;" : "=f"(y) : "f"(x));
    return y;
}

__device__ __forceinline__ void mma_tf32(float c[4], const unsigned a[4], const unsigned b[2]) {
    asm volatile(
        "mma.sync.aligned.m16n8k8.row.col.f32.tf32.tf32.f32 "
        "{%0,%1,%2,%3}, {%4,%5,%6,%7}, {%8,%9}, {%0,%1,%2,%3};"
        : "+f"(c[0]), "+f"(c[1]), "+f"(c[2]), "+f"(c[3])
        : "r"(a[0]), "r"(a[1]), "r"(a[2]), "r"(a[3]),
          "r"(b[0]), "r"(b[1]));
}

__device__ __forceinline__ void ldsm4(unsigned r[4], unsigned addr) {
    asm volatile("ldmatrix.sync.aligned.m8n8.x4.shared.b16 {%0,%1,%2,%3}, [%4];"
                 : "=r"(r[0]), "=r"(r[1]), "=r"(r[2]), "=r"(r[3]) : "r"(addr));
}

__device__ __forceinline__ void cp16(unsigned dst, const float* src) {
    asm volatile("cp.async.cg.shared.global [%0], [%1], 16;" :: "r"(dst), "l"(src));
}
#define CP_COMMIT() asm volatile("cp.async.commit_group;")
#define CP_WAIT(n)  asm volatile("cp.async.wait_group %0;" :: "n"(n))

// ---------------------------------------------------------------------------
// Pre-pass: tf32-round x and the four weight matrices into scratch.
// One float4 per thread. 5,505,024 floats = 1,376,256 float4 = 5376 blocks.
// ---------------------------------------------------------------------------
#define NX4 (SEQ * EMB / 4)      // 786432
#define NW4 (EMB * EMB / 4)      // 147456

__global__ __launch_bounds__(256) void cvt_prepass(
    const float4* __restrict__ x,
    const float4* __restrict__ wq, const float4* __restrict__ wk,
    const float4* __restrict__ wv, const float4* __restrict__ wo)
{
    const int i = blockIdx.x * 256 + threadIdx.x;
    const float4* src;
    float4* dst;
    int off;
    if (i < NX4)               { src = x;  dst = (float4*)g_x;  off = i; }
    else if (i < NX4 + NW4)    { src = wq; dst = (float4*)g_wq; off = i - NX4; }
    else if (i < NX4 + 2*NW4)  { src = wk; dst = (float4*)g_wk; off = i - NX4 - NW4; }
    else if (i < NX4 + 3*NW4)  { src = wv; dst = (float4*)g_wv; off = i - NX4 - 2*NW4; }
    else                       { src = wo; dst = (float4*)g_wo; off = i - NX4 - 3*NW4; }
    float4 v = src[off];
    v.x = f2tf(v.x); v.y = f2tf(v.y); v.z = f2tf(v.z); v.w = f2tf(v.w);
    dst[off] = v;
}

// ---------------------------------------------------------------------------
// GEMM: out[m][n] = sum_k A[m][k] * W[k][n]  (M=4096, N=64/block, K=768)
// BM=128 BN=64 BK=32, 256 thr = 8 warps (4x2), warp tile 32x32.
// cp.async double-buffered; A-frags via ldmatrix.x4. Inputs pre-rounded tf32.
// ---------------------------------------------------------------------------
#define AS_F 4608      // 128*36
#define BS_F 2304      // 32*72
#define STG_F (AS_F + BS_F)
#define GEMM_SMEM (2 * STG_F * 4)

template <bool QKV>
__global__ __launch_bounds__(256, 4) void gemm_kernel(
    const float* __restrict__ bias,
    float* __restrict__ outp)
{
    extern __shared__ float smf[];
    const unsigned sm_u = (unsigned)__cvta_generic_to_shared(smf);

    const float* A = QKV ? (const float*)g_x : (const float*)g_ctx;
    const float* W;
    if (QKV) W = (blockIdx.z == 0) ? (const float*)g_wq
               : (blockIdx.z == 1) ? (const float*)g_wk : (const float*)g_wv;
    else     W = (const float*)g_wo;

    const int m0   = blockIdx.y * 128;
    const int n0   = blockIdx.x * 64;
    const int t    = threadIdx.x;
    const int lane = t & 31;
    const int warp = t >> 5;
    const int wm   = warp >> 1;
    const int wn   = warp & 1;
    const int g    = lane >> 2;
    const int cq   = lane & 3;

    const int a_off36 = ((lane & 7) + 8 * ((lane >> 3) & 1)) * 36 + 4 * (lane >> 4);

    float c[2][4][4];
    #pragma unroll
    for (int mt = 0; mt < 2; mt++)
        #pragma unroll
        for (int nt = 0; nt < 4; nt++)
            #pragma unroll
            for (int i = 0; i < 4; i++) c[mt][nt][i] = 0.f;

    #define G_ISSUE(k0_, st_) do {                                              \
        _Pragma("unroll")                                                       \
        for (int j_ = 0; j_ < 4; j_++) {                                        \
            const int cc = j_ * 256 + t;                                        \
            const int r_ = cc >> 3, co_ = cc & 7;                               \
            cp16(sm_u + ((st_) * STG_F + r_ * 36 + co_ * 4) * 4,                \
                 A + (size_t)(m0 + r_) * EMB + (k0_) + co_ * 4);                \
        }                                                                       \
        _Pragma("unroll")                                                       \
        for (int j_ = 0; j_ < 2; j_++) {                                        \
            const int cc = j_ * 256 + t;                                        \
            const int r_ = cc >> 4, co_ = cc & 15;                              \
            cp16(sm_u + ((st_) * STG_F + AS_F + r_ * 72 + co_ * 4) * 4,         \
                 W + (size_t)((k0_) + r_) * EMB + n0 + co_ * 4);                \
        }                                                                       \
    } while (0)

    G_ISSUE(0, 0);
    CP_COMMIT();

    const int NKT = EMB / 32;   // 24
    for (int kt = 0; kt < NKT; kt++) {
        const int st = kt & 1;
        if (kt < NKT - 1) {
            G_ISSUE((kt + 1) * 32, st ^ 1);
            CP_COMMIT();
            CP_WAIT(1);
        } else {
            CP_WAIT(0);
        }
        __syncthreads();

        const unsigned As_u = sm_u + (st * STG_F) * 4;
        const float*   Bsf  = smf + st * STG_F + AS_F;

        #pragma unroll
        for (int ks = 0; ks < 4; ks++) {
            unsigned aa0[4], aa1[4];
            ldsm4(aa0, As_u + ((wm * 32) * 36 + ks * 8 + a_off36) * 4);
            ldsm4(aa1, As_u + ((wm * 32 + 16) * 36 + ks * 8 + a_off36) * 4);
            #pragma unroll
            for (int nt = 0; nt < 4; nt++) {
                const int nc = wn * 32 + nt * 8 + g;
                unsigned bb[2];
                bb[0] = __float_as_uint(Bsf[(ks * 8 + cq) * 72 + nc]);
                bb[1] = __float_as_uint(Bsf[(ks * 8 + cq + 4) * 72 + nc]);
                mma_tf32(c[0][nt], aa0, bb);
                mma_tf32(c[1][nt], aa1, bb);
            }
        }
        __syncthreads();   // stage st consumed before it is refilled
    }

    const float QSC = 0.125f * 1.44269504088896f;   // 1/(sqrt(D)*ln2)
    #pragma unroll
    for (int mt = 0; mt < 2; mt++) {
        const int row = m0 + wm * 32 + mt * 16 + g;
        #pragma unroll
        for (int nt = 0; nt < 4; nt++) {
            const int col = wn * 32 + nt * 8 + 2 * cq;
            if (QKV) {
                const int h = blockIdx.x;   // BN==HD: one head per n-block
                if (blockIdx.z == 0) {
                    float2 v0 = make_float2(f2tf(c[mt][nt][0] * QSC), f2tf(c[mt][nt][1] * QSC));
                    float2 v1 = make_float2(f2tf(c[mt][nt][2] * QSC), f2tf(c[mt][nt][3] * QSC));
                    *(float2*)(g_q + ((size_t)h * SEQ + row) * HD + col)     = v0;
                    *(float2*)(g_q + ((size_t)h * SEQ + row + 8) * HD + col) = v1;
                } else if (blockIdx.z == 1) {
                    float2 v0 = make_float2(f2tf(c[mt][nt][0]), f2tf(c[mt][nt][1]));
                    float2 v1 = make_float2(f2tf(c[mt][nt][2]), f2tf(c[mt][nt][3]));
                    *(float2*)(g_k + ((size_t)h * SEQ + row) * HD + col)     = v0;
                    *(float2*)(g_k + ((size_t)h * SEQ + row + 8) * HD + col) = v1;
                } else {
                    // V transposed [h][d][s]
                    g_v[((size_t)h * HD + col)     * SEQ + row]     = f2tf(c[mt][nt][0]);
                    g_v[((size_t)h * HD + col + 1) * SEQ + row]     = f2tf(c[mt][nt][1]);
                    g_v[((size_t)h * HD + col)     * SEQ + row + 8] = f2tf(c[mt][nt][2]);
                    g_v[((size_t)h * HD + col + 1) * SEQ + row + 8] = f2tf(c[mt][nt][3]);
                }
            } else {
                const float b0 = bias[n0 + col], b1 = bias[n0 + col + 1];
                float2 v0 = make_float2(c[mt][nt][0] + b0, c[mt][nt][1] + b1);
                float2 v1 = make_float2(c[mt][nt][2] + b0, c[mt][nt][3] + b1);
                *(float2*)(outp + (size_t)row * EMB + n0 + col)       = v0;
                *(float2*)(outp + ((size_t)row + 8) * EMB + n0 + col) = v1;
            }
        }
    }
}

// ---------------------------------------------------------------------------
// Flash attention (causal), tf32 mma, ldmatrix fragments, single-buffered
// K/V (pad-68 rows) -> 52 KB smem -> 4 blocks/SM.  Scores in log2 domain.
// Block = (head, 64-query tile), 4 warps x 16 q-rows.
// ---------------------------------------------------------------------------
#define KV_F 4352            // 64*68 floats
#define ATTN_SMEM (3 * KV_F * 4)

__global__ __launch_bounds__(128, 4) void attn_kernel()
{
    extern __shared__ float smf[];
    const unsigned sm_u = (unsigned)__cvta_generic_to_shared(smf);
    const unsigned Ks_u = sm_u;
    const unsigned Vs_u = sm_u + KV_F * 4;
    const unsigned Ps_u = sm_u + 2 * KV_F * 4;
    float* Ps = smf + 2 * KV_F;

    const int h    = blockIdx.y;
    const int qt   = (gridDim.x - 1) - blockIdx.x;   // big tiles first
    const int t    = threadIdx.x;
    const int lane = t & 31;
    const int w    = t >> 5;
    const int g    = lane >> 2;
    const int cq   = lane & 3;

    const int a_off = ((lane & 7) + 8 * ((lane >> 3) & 1)) * 68 + 4 * (lane >> 4);
    const int b_off = (lane & 7) * 68 + 4 * (lane >> 3);

    // Q fragments (gmem already tf32 + scaled by 0.125/ln2)
    unsigned qa[8][4];
    {
        const int qrow = qt * 64 + w * 16 + g;
        const float* q0 = g_q + ((size_t)h * SEQ + qrow) * HD;
        const float* q1 = q0 + 8 * HD;
        #pragma unroll
        for (int ks = 0; ks < 8; ks++) {
            qa[ks][0] = __float_as_uint(q0[ks * 8 + cq]);
            qa[ks][1] = __float_as_uint(q1[ks * 8 + cq]);
            qa[ks][2] = __float_as_uint(q0[ks * 8 + cq + 4]);
            qa[ks][3] = __float_as_uint(q1[ks * 8 + cq + 4]);
        }
    }

    float of[8][4];
    #pragma unroll
    for (int nt = 0; nt < 8; nt++)
        #pragma unroll
        for (int i = 0; i < 4; i++) of[nt][i] = 0.f;
    float m0r = -1e30f, m1r = -1e30f, l0 = 0.f, l1 = 0.f;

    const float* kbase = g_k + (size_t)h * SEQ * HD;
    const float* vbase = g_v + (size_t)h * HD * SEQ;

    for (int kt = 0; kt <= qt; kt++) {
        __syncthreads();   // previous tile fully consumed
        #pragma unroll
        for (int j = 0; j < 8; j++) {
            const int cc = j * 128 + t;
            const int r = cc >> 4, co = cc & 15;
            cp16(Ks_u + (r * 68 + co * 4) * 4,
                 kbase + (size_t)(kt * 64 + r) * HD + co * 4);
            cp16(Vs_u + (r * 68 + co * 4) * 4,
                 vbase + (size_t)r * SEQ + kt * 64 + co * 4);
        }
        CP_COMMIT();
        CP_WAIT(0);
        __syncthreads();

        // S = Q K^T  (16x64 per warp), log2-domain scores
        float sf[8][4];
        #pragma unroll
        for (int nt = 0; nt < 8; nt++) {
            sf[nt][0] = sf[nt][1] = sf[nt][2] = sf[nt][3] = 0.f;
            unsigned bf[4][4];
            #pragma unroll
            for (int kp = 0; kp < 4; kp++)
                ldsm4(bf[kp], Ks_u + ((nt * 8) * 68 + kp * 16 + b_off) * 4);
            #pragma unroll
            for (int ks = 0; ks < 8; ks++)
                mma_tf32(sf[nt], qa[ks], &bf[ks >> 1][(ks & 1) * 2]);
        }

        // causal mask on diagonal tile
        if (kt == qt) {
            const int q0l = w * 16 + g, q1l = q0l + 8;
            #pragma unroll
            for (int nt = 0; nt < 8; nt++) {
                const int key = nt * 8 + 2 * cq;
                if (key     > q0l) sf[nt][0] = -1e30f;
                if (key + 1 > q0l) sf[nt][1] = -1e30f;
                if (key     > q1l) sf[nt][2] = -1e30f;
                if (key + 1 > q1l) sf[nt][3] = -1e30f;
            }
        }

        // online softmax (base-2)
        float tm0 = -1e30f, tm1 = -1e30f;
        #pragma unroll
        for (int nt = 0; nt < 8; nt++) {
            tm0 = fmaxf(tm0, fmaxf(sf[nt][0], sf[nt][1]));
            tm1 = fmaxf(tm1, fmaxf(sf[nt][2], sf[nt][3]));
        }
        tm0 = fmaxf(tm0, __shfl_xor_sync(0xffffffffu, tm0, 1));
        tm0 = fmaxf(tm0, __shfl_xor_sync(0xffffffffu, tm0, 2));
        tm1 = fmaxf(tm1, __shfl_xor_sync(0xffffffffu, tm1, 1));
        tm1 = fmaxf(tm1, __shfl_xor_sync(0xffffffffu, tm1, 2));

        const float mn0 = fmaxf(m0r, tm0), mn1 = fmaxf(m1r, tm1);
        const float co0 = ex2f(m0r - mn0), co1 = ex2f(m1r - mn1);
        m0r = mn0; m1r = mn1;
        l0 *= co0; l1 *= co1;
        #pragma unroll
        for (int nt = 0; nt < 8; nt++) {
            of[nt][0] *= co0; of[nt][1] *= co0;
            of[nt][2] *= co1; of[nt][3] *= co1;
        }

        const int q0l = w * 16 + g;
        #pragma unroll
        for (int nt = 0; nt < 8; nt++) {
            const float p0 = ex2f(sf[nt][0] - m0r);
            const float p1 = ex2f(sf[nt][1] - m0r);
            const float p2 = ex2f(sf[nt][2] - m1r);
            const float p3 = ex2f(sf[nt][3] - m1r);
            l0 += p0 + p1;
            l1 += p2 + p3;
            const int key = nt * 8 + 2 * cq;
            *(float2*)&Ps[q0l * 68 + key]       = make_float2(p0, p1);
            *(float2*)&Ps[(q0l + 8) * 68 + key] = make_float2(p2, p3);
        }
        __syncwarp();

        // P as A-fragments via ldmatrix
        unsigned pa[8][4];
        #pragma unroll
        for (int ks = 0; ks < 8; ks++)
            ldsm4(pa[ks], Ps_u + ((w * 16) * 68 + ks * 8 + a_off) * 4);

        // O += P V   (V rows = d, cols = s)
        #pragma unroll
        for (int nt = 0; nt < 8; nt++) {
            unsigned bf[4][4];
            #pragma unroll
            for (int kp = 0; kp < 4; kp++)
                ldsm4(bf[kp], Vs_u + ((nt * 8) * 68 + kp * 16 + b_off) * 4);
            #pragma unroll
            for (int ks = 0; ks < 8; ks++)
                mma_tf32(of[nt], pa[ks], &bf[ks >> 1][(ks & 1) * 2]);
        }
    }

    // finalize
    l0 += __shfl_xor_sync(0xffffffffu, l0, 1);
    l0 += __shfl_xor_sync(0xffffffffu, l0, 2);
    l1 += __shfl_xor_sync(0xffffffffu, l1, 1);
    l1 += __shfl_xor_sync(0xffffffffu, l1, 2);
    const float inv0 = 1.f / l0, inv1 = 1.f / l1;

    const int row0 = qt * 64 + w * 16 + g;
    #pragma unroll
    for (int nt = 0; nt < 8; nt++) {
        const int d = nt * 8 + 2 * cq;
        *(float2*)(g_ctx + (size_t)row0 * EMB + h * HD + d) =
            make_float2(f2tf(of[nt][0] * inv0), f2tf(of[nt][1] * inv0));
        *(float2*)(g_ctx + ((size_t)row0 + 8) * EMB + h * HD + d) =
            make_float2(f2tf(of[nt][2] * inv1), f2tf(of[nt][3] * inv1));
    }
}

// ---------------------------------------------------------------------------
extern "C" void kernel_launch(void* const* d_in, const int* in_sizes, int n_in,
                              void* d_out, int out_size)
{
    (void)in_sizes; (void)n_in; (void)out_size;
    const float* x  = (const float*)d_in[0];
    const float* Wq = (const float*)d_in[1];
    const float* Wk = (const float*)d_in[2];
    const float* Wv = (const float*)d_in[3];
    const float* Wo = (const float*)d_in[4];
    const float* bo = (const float*)d_in[5];
    // d_in[6] = causal mask, structurally known -> unused

    static int attr_set = 0;
    if (!attr_set) {
        cudaFuncSetAttribute(gemm_kernel<true>,
                             cudaFuncAttributeMaxDynamicSharedMemorySize, GEMM_SMEM);
        cudaFuncSetAttribute(gemm_kernel<false>,
                             cudaFuncAttributeMaxDynamicSharedMemorySize, GEMM_SMEM);
        cudaFuncSetAttribute(attn_kernel,
                             cudaFuncAttributeMaxDynamicSharedMemorySize, ATTN_SMEM);
        attr_set = 1;
    }

    const int n4 = NX4 + 4 * NW4;   // 1,376,256 float4
    cvt_prepass<<<n4 / 256, 256>>>((const float4*)x, (const float4*)Wq,
                                   (const float4*)Wk, (const float4*)Wv,
                                   (const float4*)Wo);
    gemm_kernel<true><<<dim3(EMB / 64, SEQ / 128, 3), 256, GEMM_SMEM>>>(nullptr, nullptr);
    attn_kernel<<<dim3(SEQ / 64, NH), 128, ATTN_SMEM>>>();
    gemm_kernel<false><<<dim3(EMB / 64, SEQ / 128, 1), 256, GEMM_SMEM>>>(bo, (float*)d_out);
}